// round 1
// baseline (speedup 1.0000x reference)
#include <cuda_runtime.h>

// Problem constants
#define BB 2048
#define TT 2
#define NTOK 64
#define CDIM 256
#define NH 8
#define HD 32

// Scratch (device globals; allocation APIs are forbidden)
__device__ float g_q[(size_t)BB * NTOK * CDIM];            // 33,554,432 floats
__device__ float g_kv[(size_t)BB * TT * NTOK * 2 * CDIM];  // 134,217,728 floats
__device__ float g_attn[(size_t)BB * TT * NTOK * CDIM];    // 67,108,864 floats

// ---------------------------------------------------------------------------
// SGEMM: C[M,N] = A[M,K] @ W[N,K]^T + bias[N]
// Both A and W are row-major with K contiguous. 128x128 tile, BK=8,
// 256 threads, 8x8 micro-tile per thread. All dims divide tiles exactly.
// ---------------------------------------------------------------------------
__global__ __launch_bounds__(256) void sgemm_nt(
    const float* __restrict__ A, const float* __restrict__ W,
    const float* __restrict__ bias, float* __restrict__ C,
    int M, int N, int K)
{
    __shared__ float As[8][128];
    __shared__ float Ws[8][128];

    const int tid = threadIdx.x;
    const int bm = blockIdx.y * 128;
    const int bn = blockIdx.x * 128;

    // global load mapping: each thread loads one float4 of A and one of W per k-tile
    const int lr = tid >> 1;          // row within tile (0..127)
    const int lc = (tid & 1) * 4;     // k offset (0 or 4)
    const float* Ap = A + (size_t)(bm + lr) * K + lc;
    const float* Wp = W + (size_t)(bn + lr) * K + lc;

    const int tr = (tid >> 4) * 8;    // micro-tile row
    const int tc = (tid & 15) * 8;    // micro-tile col

    float acc[8][8];
#pragma unroll
    for (int i = 0; i < 8; i++)
#pragma unroll
        for (int j = 0; j < 8; j++) acc[i][j] = 0.0f;

    for (int k0 = 0; k0 < K; k0 += 8) {
        float4 a4 = *reinterpret_cast<const float4*>(Ap);
        float4 w4 = *reinterpret_cast<const float4*>(Wp);
        As[lc + 0][lr] = a4.x; As[lc + 1][lr] = a4.y;
        As[lc + 2][lr] = a4.z; As[lc + 3][lr] = a4.w;
        Ws[lc + 0][lr] = w4.x; Ws[lc + 1][lr] = w4.y;
        Ws[lc + 2][lr] = w4.z; Ws[lc + 3][lr] = w4.w;
        __syncthreads();

#pragma unroll
        for (int k = 0; k < 8; k++) {
            float af[8], bf[8];
#pragma unroll
            for (int i = 0; i < 8; i++) af[i] = As[k][tr + i];
#pragma unroll
            for (int j = 0; j < 8; j++) bf[j] = Ws[k][tc + j];
#pragma unroll
            for (int i = 0; i < 8; i++)
#pragma unroll
                for (int j = 0; j < 8; j++)
                    acc[i][j] = fmaf(af[i], bf[j], acc[i][j]);
        }
        __syncthreads();
        Ap += 8;
        Wp += 8;
    }

#pragma unroll
    for (int i = 0; i < 8; i++) {
        float* Cp = C + (size_t)(bm + tr + i) * N + bn + tc;
#pragma unroll
        for (int j4 = 0; j4 < 2; j4++) {
            float4 v;
            v.x = acc[i][j4 * 4 + 0] + bias[bn + tc + j4 * 4 + 0];
            v.y = acc[i][j4 * 4 + 1] + bias[bn + tc + j4 * 4 + 1];
            v.z = acc[i][j4 * 4 + 2] + bias[bn + tc + j4 * 4 + 2];
            v.w = acc[i][j4 * 4 + 3] + bias[bn + tc + j4 * 4 + 3];
            *reinterpret_cast<float4*>(Cp + j4 * 4) = v;
        }
    }
}

// ---------------------------------------------------------------------------
// Attention: one block per (b, t, h), 64 threads = one query row each.
// Reads g_q (b, n, h*32+d) and g_kv ((b*T+t), n, {k:0..255, v:256..511}).
// Writes g_attn ((b*T+t), n, h*32+d) — head-merged layout for the out-proj.
// Each thread owns an entire softmax row => no cross-thread reductions.
// ---------------------------------------------------------------------------
__global__ __launch_bounds__(64) void attn_kernel(const float* __restrict__ rpb)
{
    __shared__ float4 sK[512];       // 64 rows x 8 float4
    __shared__ float4 sV[512];
    __shared__ float  sL[64 * 65];   // logits, padded: bank=(n+m)%32 conflict-free

    const int bx = blockIdx.x;
    const int h = bx & 7;
    const int t = (bx >> 3) & 1;
    const int b = bx >> 4;
    const int n = threadIdx.x;

    // cooperative, coalesced K/V tile load
    const float* kb = g_kv + (size_t)((b * 2 + t) * 64) * 512 + h * 32;
    for (int i = n; i < 512; i += 64) {
        int r = i >> 3, c = i & 7;
        sK[i] = *reinterpret_cast<const float4*>(kb + (size_t)r * 512 + c * 4);
        sV[i] = *reinterpret_cast<const float4*>(kb + 256 + (size_t)r * 512 + c * 4);
    }

    // q row -> registers (pre-scaled)
    const float scale = 0.17677669529663687f;  // 32^-0.5
    float q[32];
    const float* qb = g_q + (size_t)(b * 64 + n) * 256 + h * 32;
#pragma unroll
    for (int c = 0; c < 8; c++) {
        float4 f = *reinterpret_cast<const float4*>(qb + c * 4);
        q[4 * c + 0] = f.x * scale; q[4 * c + 1] = f.y * scale;
        q[4 * c + 2] = f.z * scale; q[4 * c + 3] = f.w * scale;
    }
    __syncthreads();

    // logits + running max. bias idx = (ni-mi+7)*15 + (nj-mj+7)
    const int base_idx = ((n >> 3) + 7) * 15 + ((n & 7) + 7);
    float mx = -1e30f;
    float* myL = &sL[n * 65];
#pragma unroll 4
    for (int m = 0; m < 64; m++) {
        const float4* kr = &sK[m * 8];
        float s0 = 0.f, s1 = 0.f, s2 = 0.f, s3 = 0.f;
#pragma unroll
        for (int c = 0; c < 8; c++) {
            float4 kf = kr[c];   // all-lane broadcast read
            s0 = fmaf(q[4 * c + 0], kf.x, s0);
            s1 = fmaf(q[4 * c + 1], kf.y, s1);
            s2 = fmaf(q[4 * c + 2], kf.z, s2);
            s3 = fmaf(q[4 * c + 3], kf.w, s3);
        }
        int idx = base_idx - ((m >> 3) * 15 + (m & 7));
        float s = (s0 + s1) + (s2 + s3) + __ldg(&rpb[idx * 8 + h]);
        mx = fmaxf(mx, s);
        myL[m] = s;
    }

    // exp + sum
    float sum0 = 0.f, sum1 = 0.f;
#pragma unroll 4
    for (int m = 0; m < 64; m += 2) {
        float e0 = __expf(myL[m] - mx);
        float e1 = __expf(myL[m + 1] - mx);
        myL[m] = e0; myL[m + 1] = e1;
        sum0 += e0; sum1 += e1;
    }
    float inv = 1.0f / (sum0 + sum1);

    // PV
    float o[32];
#pragma unroll
    for (int c = 0; c < 32; c++) o[c] = 0.f;
#pragma unroll 2
    for (int m = 0; m < 64; m++) {
        float w = myL[m];
        const float4* vr = &sV[m * 8];
#pragma unroll
        for (int c = 0; c < 8; c++) {
            float4 vf = vr[c];   // all-lane broadcast read
            o[4 * c + 0] = fmaf(w, vf.x, o[4 * c + 0]);
            o[4 * c + 1] = fmaf(w, vf.y, o[4 * c + 1]);
            o[4 * c + 2] = fmaf(w, vf.z, o[4 * c + 2]);
            o[4 * c + 3] = fmaf(w, vf.w, o[4 * c + 3]);
        }
    }

    float* ob = g_attn + (size_t)((b * 2 + t) * 64 + n) * 256 + h * 32;
#pragma unroll
    for (int c = 0; c < 8; c++) {
        float4 v;
        v.x = o[4 * c + 0] * inv; v.y = o[4 * c + 1] * inv;
        v.z = o[4 * c + 2] * inv; v.w = o[4 * c + 3] * inv;
        *reinterpret_cast<float4*>(ob + c * 4) = v;
    }
}

// ---------------------------------------------------------------------------
extern "C" void kernel_launch(void* const* d_in, const int* in_sizes, int n_in,
                              void* d_out, int out_size)
{
    const float* x      = (const float*)d_in[0];
    const float* memory = (const float*)d_in[1];
    const float* q_w    = (const float*)d_in[2];
    const float* q_b    = (const float*)d_in[3];
    const float* kv_w   = (const float*)d_in[4];
    const float* kv_b   = (const float*)d_in[5];
    const float* proj_w = (const float*)d_in[6];
    const float* proj_b = (const float*)d_in[7];
    const float* rpb    = (const float*)d_in[8];
    float* out = (float*)d_out;

    float *pq, *pkv, *pattn;
    cudaGetSymbolAddress((void**)&pq, g_q);
    cudaGetSymbolAddress((void**)&pkv, g_kv);
    cudaGetSymbolAddress((void**)&pattn, g_attn);

    // q = x @ q_w^T + q_b              (131072 x 256, K=256)
    sgemm_nt<<<dim3(2, 1024), 256>>>(x, q_w, q_b, pq, BB * NTOK, CDIM, CDIM);
    // kv = memory @ kv_w^T + kv_b      (262144 x 512, K=256)
    sgemm_nt<<<dim3(4, 2048), 256>>>(memory, kv_w, kv_b, pkv, BB * TT * NTOK, 2 * CDIM, CDIM);
    // softmax attention per (b, t, h)
    attn_kernel<<<BB * TT * NH, 64>>>(rpb);
    // out = attn @ proj_w^T + proj_b   (262144 x 256, K=256)
    sgemm_nt<<<dim3(2, 2048), 256>>>(pattn, proj_w, proj_b, out, BB * TT * NTOK, CDIM, CDIM);
}